// round 12
// baseline (speedup 1.0000x reference)
#include <cuda_runtime.h>
#include <cuda_bf16.h>
#include <cstdint>
#include <cstddef>

#define LOG2E 1.4426950408889634f
#define LN2   0.6931471805599453f

// ---- static scratch ----
// cost in diag layout [b][i+j][j], log2e-scaled, padded by 4 rows for branchless prefetch
__device__ float g_cost[64 * 512 * 256 + 1024];
__device__ float g_xn[64 * 256];                // log2e * |x_i|^2
__device__ float g_yn[64 * 256];
__device__ unsigned short g_xb[64 * 256 * 128]; // bf16 bits of x
__device__ unsigned short g_yb[64 * 256 * 128]; // bf16 bits of y

__device__ __forceinline__ float ex2f(float x) {
    float y; asm("ex2.approx.f32 %0, %1;" : "=f"(y) : "f"(x)); return y;
}
__device__ __forceinline__ float lg2f(float x) {
    float y; asm("lg2.approx.f32 %0, %1;" : "=f"(y) : "f"(x)); return y;
}
__device__ __forceinline__ uint32_t sptr(const void* p) {
    return (uint32_t)__cvta_generic_to_shared(p);
}
// stable soft-min of 3 in log2 domain
__device__ __forceinline__ float sm3(float a, float b, float c) {
    float mn = fminf(a, b), mx = fmaxf(a, b);
    float lo  = fminf(mn, c);
    float mid = fmaxf(mn, fminf(mx, c));
    float hi  = fmaxf(mx, c);
    return lo - lg2f(1.0f + ex2f(lo - mid) + ex2f(lo - hi));
}

// ================= K0: norms + bf16 convert (warp per row) =================
__global__ void __launch_bounds__(256) prep_kernel(const float* __restrict__ x,
                                                   const float* __restrict__ y,
                                                   float* __restrict__ out) {
    int gw = blockIdx.x * 8 + (threadIdx.x >> 5);
    int lane = threadIdx.x & 31;
    bool isx = gw < 16384;
    int rowg = isx ? gw : gw - 16384;  // b*256 + r
    const float* src = (isx ? x : y) + (size_t)rowg * 128 + lane * 4;
    float4 f = *(const float4*)src;
    float s = f.x * f.x;
    s = fmaf(f.y, f.y, s); s = fmaf(f.z, f.z, s); s = fmaf(f.w, f.w, s);
#pragma unroll
    for (int off = 16; off >= 1; off >>= 1) s += __shfl_xor_sync(0xffffffffu, s, off);
    if (lane == 0) (isx ? g_xn : g_yn)[rowg] = s * LOG2E;
    ushort4 s4;
    s4.x = __bfloat16_as_ushort(__float2bfloat16(f.x));
    s4.y = __bfloat16_as_ushort(__float2bfloat16(f.y));
    s4.z = __bfloat16_as_ushort(__float2bfloat16(f.z));
    s4.w = __bfloat16_as_ushort(__float2bfloat16(f.w));
    *(ushort4*)((isx ? g_xb : g_yb) + (size_t)rowg * 128 + lane * 4) = s4;
    if (blockIdx.x == 0 && threadIdx.x == 0) out[0] = 0.f;
}

// ================= K1: bf16 mma cost GEMM, diag-coalesced epilogue =================
// 256 blocks = 64 batches x (2x2 tiles of 128x128). 8 warps, warp tile 32(m) x 64(n).
__global__ void __launch_bounds__(256) cost_gemm_kernel() {
    __shared__ __align__(16) char smraw[33280];
    unsigned short* Xs = (unsigned short*)smraw;       // [128][64] bf16, swizzled
    unsigned short* Ys = Xs + 128 * 64;
    float* Cs = (float*)smraw;                          // [64][130]

    int bx = blockIdx.x;
    int b = bx >> 2, tm = (bx >> 1) & 1, tn = bx & 1;
    int t = threadIdx.x, lane = t & 31, w = t >> 5;
    int wr = w >> 1, wc = w & 1;

    const unsigned short* Xg = g_xb + ((size_t)(b * 256 + tm * 128)) * 128;
    const unsigned short* Yg = g_yb + ((size_t)(b * 256 + tn * 128)) * 128;

    float acc[2][8][4];
#pragma unroll
    for (int am = 0; am < 2; am++)
#pragma unroll
        for (int bn = 0; bn < 8; bn++)
#pragma unroll
            for (int k = 0; k < 4; k++) acc[am][bn][k] = 0.f;

    int arow0 = 32 * wr + (lane & 15);
    int ahalf = lane >> 4;
    int brow0 = 64 * wc + (lane & 7) + ((lane >> 4) << 3);
    int bhalf = (lane >> 3) & 1;

    for (int kc = 0; kc < 128; kc += 64) {
        __syncthreads();
#pragma unroll
        for (int p = 0; p < 4; p++) {
            int u = t + 256 * p;
            int row = u >> 3, c16 = u & 7;
            uint4 vx = *(const uint4*)(Xg + (size_t)row * 128 + kc + c16 * 8);
            uint4 vy = *(const uint4*)(Yg + (size_t)row * 128 + kc + c16 * 8);
            int soff = row * 128 + ((c16 ^ (row & 7)) << 4);
            *(uint4*)((char*)Xs + soff) = vx;
            *(uint4*)((char*)Ys + soff) = vy;
        }
        __syncthreads();
#pragma unroll
        for (int ks = 0; ks < 4; ks++) {
            uint32_t a[2][4], bf[8][2];
#pragma unroll
            for (int am = 0; am < 2; am++) {
                int row = arow0 + 16 * am;
                int kb16 = ks * 2 + ahalf;
                uint32_t ad = sptr((char*)Xs + row * 128 + ((kb16 ^ (row & 7)) << 4));
                asm volatile("ldmatrix.sync.aligned.m8n8.x4.shared.b16 {%0,%1,%2,%3},[%4];"
                    : "=r"(a[am][0]), "=r"(a[am][1]), "=r"(a[am][2]), "=r"(a[am][3]) : "r"(ad));
            }
#pragma unroll
            for (int bp = 0; bp < 4; bp++) {
                int row = brow0 + 16 * bp;
                int kb16 = ks * 2 + bhalf;
                uint32_t ad = sptr((char*)Ys + row * 128 + ((kb16 ^ (row & 7)) << 4));
                asm volatile("ldmatrix.sync.aligned.m8n8.x4.shared.b16 {%0,%1,%2,%3},[%4];"
                    : "=r"(bf[2 * bp][0]), "=r"(bf[2 * bp][1]),
                      "=r"(bf[2 * bp + 1][0]), "=r"(bf[2 * bp + 1][1]) : "r"(ad));
            }
#pragma unroll
            for (int am = 0; am < 2; am++)
#pragma unroll
                for (int bn = 0; bn < 8; bn++)
                    asm volatile("mma.sync.aligned.m16n8k16.row.col.f32.bf16.bf16.f32 "
                        "{%0,%1,%2,%3},{%4,%5,%6,%7},{%8,%9},{%0,%1,%2,%3};"
                        : "+f"(acc[am][bn][0]), "+f"(acc[am][bn][1]),
                          "+f"(acc[am][bn][2]), "+f"(acc[am][bn][3])
                        : "r"(a[am][0]), "r"(a[am][1]), "r"(a[am][2]), "r"(a[am][3]),
                          "r"(bf[bn][0]), "r"(bf[bn][1]));
        }
    }

    // epilogue: stage to smem in 2 row-halves, then coalesced diag-major stores
    __syncthreads();
    float* cb = g_cost + (size_t)b * 512 * 256;
    const float* xn = g_xn + b * 256;
    const float* yn = g_yn + b * 256;

#pragma unroll
    for (int h = 0; h < 2; h++) {
        if ((wr >> 1) == h) {
            int rbase = 32 * (wr & 1);
#pragma unroll
            for (int am = 0; am < 2; am++)
#pragma unroll
                for (int bn = 0; bn < 8; bn++) {
                    int rr = rbase + 16 * am + (lane >> 2);
                    int cc = 64 * wc + 8 * bn + 2 * (lane & 3);
                    *(float2*)&Cs[rr * 130 + cc] = make_float2(acc[am][bn][0], acc[am][bn][1]);
                    *(float2*)&Cs[(rr + 8) * 130 + cc] = make_float2(acc[am][bn][2], acc[am][bn][3]);
                }
        }
        __syncthreads();
        int tt = t & 127;
        for (int s2 = 0; s2 < 192; s2 += 2) {
            int s = s2 + (t >> 7);                 // local diag within half: 0..191
            int lj_lo = max(0, s - 63), lj_hi = min(127, s);
            int lj = lj_lo + tt;
            if (s < 191 && lj <= lj_hi) {
                int li = s - lj;
                int i = tm * 128 + 64 * h + li;
                int j = tn * 128 + lj;
                float v = xn[i] + yn[j] - (2.0f * LOG2E) * Cs[li * 130 + lj];
                cb[(size_t)(i + j) * 256 + j] = v;
            }
        }
        __syncthreads();
    }
}

// ================= K2: 2-diag-per-barrier wavefront, 2 batches per block =================
// 32 blocks x 256 threads. Warps 0-3 = batch 2*bx, warps 4-7 = batch 2*bx+1.
// Within a batch: 128 threads, thread tt owns columns jA=2tt+1, jB=2tt+2; one shared
// __syncthreads per iteration advances both batches by 2 anti-diagonals. The two
// independent dependence chains live on the same SMSPs (2 warps/SMSP) -> latency hiding.
__global__ void __launch_bounds__(256) dp_kernel(float* __restrict__ out) {
    __shared__ float4 bndP[2][2][5];   // [batch][parity][slot] {r1A,r2A,r1B,r2B}
    __shared__ float  bndC[2][2][5];   // cost element for the redundant boundary cell

    int t = threadIdx.x, b = blockIdx.x;
    int q = t >> 7;                    // batch slot within block (0/1)
    int tt = t & 127;                  // thread index within batch
    int lane = t & 31, w = tt >> 5;    // warp index within batch (0..3)
    const float INF = __int_as_float(0x7f800000);
    const float* cost = g_cost + (size_t)(2 * b + q) * 512 * 256 + 2 * tt;

    if (t < 20) {
        ((float4*)bndP)[t] = make_float4(INF, INF, INF, INF);
        ((float*)bndC)[t] = 0.0f;
    }
    __syncthreads();

    float r1A = INF, r2A = INF, r1B = INF, r2B = INF;
    float2 e0 = *(const float2*)(cost + 0 * 256);   // row 2k   (d-2)
    float2 o0 = *(const float2*)(cost + 1 * 256);   // row 2k+1 (d-1)
    float2 e1 = *(const float2*)(cost + 2 * 256);
    float2 o1 = *(const float2*)(cost + 3 * 256);

    int jA = 2 * tt + 1;
    bool p0 = (tt == 0);
    bool isL0 = (lane == 0);
    bool isL31 = (lane == 31);
    int jR = 64 * w;                   // boundary column left of this warp

    for (int k = 0; k < 256; ++k) {
        int d = 2 * k + 2;
        int par = k & 1;

        float sh1 = __shfl_up_sync(0xffffffffu, r1B, 1);
        float sh2 = __shfl_up_sync(0xffffffffu, r2B, 1);
        float4 P = bndP[q][par][w];    // uniform per warp (broadcast)
        float Pc = bndC[q][par][w];
        float lbA1 = isL0 ? P.z : sh1;     // R[d-1][jA-1]
        float lbA2 = isL0 ? P.w : sh2;     // R[d-2][jA-1]
        if (p0) { lbA1 = INF; lbA2 = (k == 0) ? 0.0f : INF; }

        // ---- diagonal d ----
        float rdA = e0.x + sm3(r1A, lbA1, lbA2);
        float rdB = e0.y + sm3(r1B, r1A, r2A);
        float rr  = Pc  + sm3(P.z,  P.x,  P.y);    // redundant boundary cell (col jR, diag d)

        unsigned iA = (unsigned)(d - jA);
        float r1A_mid = ((iA - 1u) < 256u) ? rdA : r1A;   // R[d][jA] effective
        float r1B_mid = ((iA - 2u) < 256u) ? rdB : r1B;   // R[d][jB] effective
        float rr_eff  = ((unsigned)(d - jR - 1) < 256u) ? rr : INF;  // R[d][jR] eff

        // ---- diagonal d+1 ----
        float shm = __shfl_up_sync(0xffffffffu, r1B_mid, 1);
        float lbA1p = isL0 ? rr_eff : shm;  // R[d][jA-1]
        if (p0) lbA1p = INF;
        float rdAp = o0.x + sm3(r1A_mid, lbA1p, lbA1);     // dl = R[d-1][jA-1]
        float rdBp = o0.y + sm3(r1B_mid, r1A_mid, r1A);    // dl = R[d-1][jA]

        r2A = r1A_mid;
        r1A = ((iA + 0u) < 256u) ? rdAp : r1A_mid;   // (d+1)-jA - 1 = iA
        r2B = r1B_mid;
        r1B = ((iA - 1u) < 256u) ? rdBp : r1B_mid;   // (d+1)-jB - 1 = iA-1

        // publish for next iteration's consumer (warp w+1 of the same batch)
        if (isL31) {
            bndP[q][par ^ 1][w + 1] = make_float4(r1A, r2A, r1B, r2B);
            bndC[q][par ^ 1][w + 1] = e1.y;   // cost row 2k+2, col jB-1
        }
        __syncthreads();

        // shift cost pipeline (pad rows make this branchless-safe)
        e0 = e1; o0 = o1;
        e1 = *(const float2*)(cost + (size_t)(2 * k + 4) * 256);
        o1 = *(const float2*)(cost + (size_t)(2 * k + 5) * 256);
    }

    // tt=127 col jB=256: r1B = R[512][256]
    if (tt == 127) atomicAdd(out, r1B * (LN2 / 64.0f));
}

extern "C" void kernel_launch(void* const* d_in, const int* in_sizes, int n_in,
                              void* d_out, int out_size) {
    const float* x = (const float*)d_in[0];
    const float* y = (const float*)d_in[1];
    float* out = (float*)d_out;
    prep_kernel<<<4096, 256>>>(x, y, out);
    cost_gemm_kernel<<<256, 256>>>();
    dp_kernel<<<32, 256>>>(out);
}

// round 13
// speedup vs baseline: 1.1264x; 1.1264x over previous
#include <cuda_runtime.h>
#include <cuda_bf16.h>
#include <cstdint>
#include <cstddef>

#define LOG2E 1.4426950408889634f
#define LN2   0.6931471805599453f

// ---- static scratch ----
// cost in diag layout [b][i+j][j], log2e-scaled, padded by 4 rows for branchless prefetch
__device__ float g_cost[64 * 512 * 256 + 1024];
__device__ float g_xn[64 * 256];                // log2e * |x_i|^2
__device__ float g_yn[64 * 256];
__device__ unsigned short g_xb[64 * 256 * 128]; // bf16 bits of x
__device__ unsigned short g_yb[64 * 256 * 128]; // bf16 bits of y

__device__ __forceinline__ uint32_t sptr(const void* p) {
    return (uint32_t)__cvta_generic_to_shared(p);
}

// MUFU-free stable soft-min of 3 in log2 domain:
//   lo - lg2(1 + 2^(lo-mid) + 2^(lo-hi))
// 2^-t (t in [0,28]) via trunc-split + cubic; lg2(s) (s in [1,4)) via exponent
// extraction + cubic on [1,2]. Max per-call error ~1.5e-3 log2 units (budget ~0.18).
__device__ __forceinline__ float sm3(float a, float b, float c) {
    float mn = fminf(a, b), mx = fmaxf(a, b);
    float lo  = fminf(mn, c);
    float mid = fmaxf(mn, fminf(mx, c));
    float hi  = fmaxf(mx, c);
    float t1 = fminf(mid - lo, 28.0f);   // NaN (INF-INF) -> 28 -> u ~ 0
    float t2 = fminf(hi  - lo, 28.0f);
    int   n1 = (int)t1, n2 = (int)t2;    // trunc = floor (t >= 0)
    float g1 = (float)(n1 + 1) - t1;     // in (0,1]
    float g2 = (float)(n2 + 1) - t2;
    // 2^g on [0,1]: exact at both ends
    float q1 = fmaf(g1, fmaf(g1, fmaf(g1, 0.0790185f, 0.2249975f), 0.6959840f), 1.0f);
    float q2 = fmaf(g2, fmaf(g2, fmaf(g2, 0.0790185f, 0.2249975f), 0.6959840f), 1.0f);
    float sc1 = __int_as_float((126 - n1) << 23);   // 2^-(n+1)
    float sc2 = __int_as_float((126 - n2) << 23);
    float s = 1.0f + fmaf(q1, sc1, q2 * sc2);       // in [1, 3]
    int  sb = __float_as_int(s);
    int  e  = (sb >> 23) - 127;                      // 0 or 1
    float m = __int_as_float((sb & 0x007FFFFF) | 0x3F800000);  // [1,2)
    // lg2(m) cubic, exact at m=1 and m=2 (continuous across e-boundary)
    float p = fmaf(m, fmaf(m, fmaf(m, 0.1539709f, -1.0348760f), 3.0268372f), -2.1459321f);
    return lo - (float)e - p;
}

// ================= K0: norms + bf16 convert (warp per row) =================
__global__ void __launch_bounds__(256) prep_kernel(const float* __restrict__ x,
                                                   const float* __restrict__ y,
                                                   float* __restrict__ out) {
    int gw = blockIdx.x * 8 + (threadIdx.x >> 5);
    int lane = threadIdx.x & 31;
    bool isx = gw < 16384;
    int rowg = isx ? gw : gw - 16384;  // b*256 + r
    const float* src = (isx ? x : y) + (size_t)rowg * 128 + lane * 4;
    float4 f = *(const float4*)src;
    float s = f.x * f.x;
    s = fmaf(f.y, f.y, s); s = fmaf(f.z, f.z, s); s = fmaf(f.w, f.w, s);
#pragma unroll
    for (int off = 16; off >= 1; off >>= 1) s += __shfl_xor_sync(0xffffffffu, s, off);
    if (lane == 0) (isx ? g_xn : g_yn)[rowg] = s * LOG2E;
    ushort4 s4;
    s4.x = __bfloat16_as_ushort(__float2bfloat16(f.x));
    s4.y = __bfloat16_as_ushort(__float2bfloat16(f.y));
    s4.z = __bfloat16_as_ushort(__float2bfloat16(f.z));
    s4.w = __bfloat16_as_ushort(__float2bfloat16(f.w));
    *(ushort4*)((isx ? g_xb : g_yb) + (size_t)rowg * 128 + lane * 4) = s4;
    if (blockIdx.x == 0 && threadIdx.x == 0) out[0] = 0.f;
}

// ================= K1: bf16 mma cost GEMM, diag-coalesced epilogue =================
// 256 blocks = 64 batches x (2x2 tiles of 128x128). 8 warps, warp tile 32(m) x 64(n).
__global__ void __launch_bounds__(256) cost_gemm_kernel() {
    __shared__ __align__(16) char smraw[33280];
    unsigned short* Xs = (unsigned short*)smraw;       // [128][64] bf16, swizzled
    unsigned short* Ys = Xs + 128 * 64;
    float* Cs = (float*)smraw;                          // [64][130]

    int bx = blockIdx.x;
    int b = bx >> 2, tm = (bx >> 1) & 1, tn = bx & 1;
    int t = threadIdx.x, lane = t & 31, w = t >> 5;
    int wr = w >> 1, wc = w & 1;

    const unsigned short* Xg = g_xb + ((size_t)(b * 256 + tm * 128)) * 128;
    const unsigned short* Yg = g_yb + ((size_t)(b * 256 + tn * 128)) * 128;

    float acc[2][8][4];
#pragma unroll
    for (int am = 0; am < 2; am++)
#pragma unroll
        for (int bn = 0; bn < 8; bn++)
#pragma unroll
            for (int k = 0; k < 4; k++) acc[am][bn][k] = 0.f;

    int arow0 = 32 * wr + (lane & 15);
    int ahalf = lane >> 4;
    int brow0 = 64 * wc + (lane & 7) + ((lane >> 4) << 3);
    int bhalf = (lane >> 3) & 1;

    for (int kc = 0; kc < 128; kc += 64) {
        __syncthreads();
#pragma unroll
        for (int p = 0; p < 4; p++) {
            int u = t + 256 * p;
            int row = u >> 3, c16 = u & 7;
            uint4 vx = *(const uint4*)(Xg + (size_t)row * 128 + kc + c16 * 8);
            uint4 vy = *(const uint4*)(Yg + (size_t)row * 128 + kc + c16 * 8);
            int soff = row * 128 + ((c16 ^ (row & 7)) << 4);
            *(uint4*)((char*)Xs + soff) = vx;
            *(uint4*)((char*)Ys + soff) = vy;
        }
        __syncthreads();
#pragma unroll
        for (int ks = 0; ks < 4; ks++) {
            uint32_t a[2][4], bf[8][2];
#pragma unroll
            for (int am = 0; am < 2; am++) {
                int row = arow0 + 16 * am;
                int kb16 = ks * 2 + ahalf;
                uint32_t ad = sptr((char*)Xs + row * 128 + ((kb16 ^ (row & 7)) << 4));
                asm volatile("ldmatrix.sync.aligned.m8n8.x4.shared.b16 {%0,%1,%2,%3},[%4];"
                    : "=r"(a[am][0]), "=r"(a[am][1]), "=r"(a[am][2]), "=r"(a[am][3]) : "r"(ad));
            }
#pragma unroll
            for (int bp = 0; bp < 4; bp++) {
                int row = brow0 + 16 * bp;
                int kb16 = ks * 2 + bhalf;
                uint32_t ad = sptr((char*)Ys + row * 128 + ((kb16 ^ (row & 7)) << 4));
                asm volatile("ldmatrix.sync.aligned.m8n8.x4.shared.b16 {%0,%1,%2,%3},[%4];"
                    : "=r"(bf[2 * bp][0]), "=r"(bf[2 * bp][1]),
                      "=r"(bf[2 * bp + 1][0]), "=r"(bf[2 * bp + 1][1]) : "r"(ad));
            }
#pragma unroll
            for (int am = 0; am < 2; am++)
#pragma unroll
                for (int bn = 0; bn < 8; bn++)
                    asm volatile("mma.sync.aligned.m16n8k16.row.col.f32.bf16.bf16.f32 "
                        "{%0,%1,%2,%3},{%4,%5,%6,%7},{%8,%9},{%0,%1,%2,%3};"
                        : "+f"(acc[am][bn][0]), "+f"(acc[am][bn][1]),
                          "+f"(acc[am][bn][2]), "+f"(acc[am][bn][3])
                        : "r"(a[am][0]), "r"(a[am][1]), "r"(a[am][2]), "r"(a[am][3]),
                          "r"(bf[bn][0]), "r"(bf[bn][1]));
        }
    }

    // epilogue: stage to smem in 2 row-halves, then coalesced diag-major stores
    __syncthreads();
    float* cb = g_cost + (size_t)b * 512 * 256;
    const float* xn = g_xn + b * 256;
    const float* yn = g_yn + b * 256;

#pragma unroll
    for (int h = 0; h < 2; h++) {
        if ((wr >> 1) == h) {
            int rbase = 32 * (wr & 1);
#pragma unroll
            for (int am = 0; am < 2; am++)
#pragma unroll
                for (int bn = 0; bn < 8; bn++) {
                    int rr = rbase + 16 * am + (lane >> 2);
                    int cc = 64 * wc + 8 * bn + 2 * (lane & 3);
                    *(float2*)&Cs[rr * 130 + cc] = make_float2(acc[am][bn][0], acc[am][bn][1]);
                    *(float2*)&Cs[(rr + 8) * 130 + cc] = make_float2(acc[am][bn][2], acc[am][bn][3]);
                }
        }
        __syncthreads();
        int tt = t & 127;
        for (int s2 = 0; s2 < 192; s2 += 2) {
            int s = s2 + (t >> 7);                 // local diag within half: 0..191
            int lj_lo = max(0, s - 63), lj_hi = min(127, s);
            int lj = lj_lo + tt;
            if (s < 191 && lj <= lj_hi) {
                int li = s - lj;
                int i = tm * 128 + 64 * h + li;
                int j = tn * 128 + lj;
                float v = xn[i] + yn[j] - (2.0f * LOG2E) * Cs[li * 130 + lj];
                cb[(size_t)(i + j) * 256 + j] = v;
            }
        }
        __syncthreads();
    }
}

// ================= K2: 2-diagonal-per-barrier wavefront soft-DTW =================
// 64 blocks (1/batch) x 128 threads (4 warps). Thread t owns columns jA=2t+1, jB=2t+2.
// Identical structure to the 129.9us best; only sm3 is now MUFU-free.
__global__ void __launch_bounds__(128) dp_kernel(float* __restrict__ out) {
    __shared__ float4 bndP[2][5];   // [parity][slot] {r1A,r2A,r1B,r2B} of warp slot-1's lane31
    __shared__ float  bndC[2][5];   // cost element for the redundant boundary cell

    int t = threadIdx.x, lane = t & 31, w = t >> 5, b = blockIdx.x;
    const float INF = __int_as_float(0x7f800000);
    const float* cost = g_cost + (size_t)b * 512 * 256 + 2 * t;

    if (t < 10) {
        ((float4*)bndP)[t] = make_float4(INF, INF, INF, INF);
        ((float*)bndC)[t] = 0.0f;
    }
    __syncthreads();

    float r1A = INF, r2A = INF, r1B = INF, r2B = INF;
    float2 e0 = *(const float2*)(cost + 0 * 256);   // row 2k   (d-2)
    float2 o0 = *(const float2*)(cost + 1 * 256);   // row 2k+1 (d-1)
    float2 e1 = *(const float2*)(cost + 2 * 256);
    float2 o1 = *(const float2*)(cost + 3 * 256);

    int jA = 2 * t + 1;
    bool p0 = (t == 0);
    bool isL0 = (lane == 0);
    bool isL31 = (lane == 31);
    int jR = 64 * w;                 // boundary column left of this warp

    for (int k = 0; k < 256; ++k) {
        int d = 2 * k + 2;
        int par = k & 1;

        float sh1 = __shfl_up_sync(0xffffffffu, r1B, 1);
        float sh2 = __shfl_up_sync(0xffffffffu, r2B, 1);
        float4 P = bndP[par][w];     // uniform per warp (broadcast)
        float Pc = bndC[par][w];
        float lbA1 = isL0 ? P.z : sh1;     // R[d-1][jA-1]
        float lbA2 = isL0 ? P.w : sh2;     // R[d-2][jA-1]
        if (p0) { lbA1 = INF; lbA2 = (k == 0) ? 0.0f : INF; }

        // ---- diagonal d ----
        float rdA = e0.x + sm3(r1A, lbA1, lbA2);
        float rdB = e0.y + sm3(r1B, r1A, r2A);
        float rr  = Pc  + sm3(P.z,  P.x,  P.y);    // redundant boundary cell (col jR, diag d)

        unsigned iA = (unsigned)(d - jA);
        float r1A_mid = ((iA - 1u) < 256u) ? rdA : r1A;   // R[d][jA] effective
        float r1B_mid = ((iA - 2u) < 256u) ? rdB : r1B;   // R[d][jB] effective
        float rr_eff  = ((unsigned)(d - jR - 1) < 256u) ? rr : INF;  // R[d][jR] eff

        // ---- diagonal d+1 ----
        float shm = __shfl_up_sync(0xffffffffu, r1B_mid, 1);
        float lbA1p = isL0 ? rr_eff : shm;  // R[d][jA-1]
        if (p0) lbA1p = INF;
        float rdAp = o0.x + sm3(r1A_mid, lbA1p, lbA1);     // dl = R[d-1][jA-1]
        float rdBp = o0.y + sm3(r1B_mid, r1A_mid, r1A);    // dl = R[d-1][jA]

        r2A = r1A_mid;
        r1A = ((iA + 0u) < 256u) ? rdAp : r1A_mid;   // (d+1)-jA - 1 = iA
        r2B = r1B_mid;
        r1B = ((iA - 1u) < 256u) ? rdBp : r1B_mid;   // (d+1)-jB - 1 = iA-1

        // publish for next iteration's consumer (warp w+1)
        if (isL31) {
            bndP[par ^ 1][w + 1] = make_float4(r1A, r2A, r1B, r2B);
            bndC[par ^ 1][w + 1] = e1.y;   // cost row 2k+2, col jB-1
        }
        __syncthreads();

        // shift cost pipeline (pad rows make this branchless-safe)
        e0 = e1; o0 = o1;
        e1 = *(const float2*)(cost + (size_t)(2 * k + 4) * 256);
        o1 = *(const float2*)(cost + (size_t)(2 * k + 5) * 256);
    }

    // t=127 col jB=256: r1B = R[512][256]
    if (t == 127) atomicAdd(out, r1B * (LN2 / 64.0f));
}

extern "C" void kernel_launch(void* const* d_in, const int* in_sizes, int n_in,
                              void* d_out, int out_size) {
    const float* x = (const float*)d_in[0];
    const float* y = (const float*)d_in[1];
    float* out = (float*)d_out;
    prep_kernel<<<4096, 256>>>(x, y, out);
    cost_gemm_kernel<<<256, 256>>>();
    dp_kernel<<<64, 128>>>(out);
}

// round 14
// speedup vs baseline: 1.2572x; 1.1161x over previous
#include <cuda_runtime.h>
#include <cuda_bf16.h>
#include <cstdint>
#include <cstddef>

#define LOG2E 1.4426950408889634f
#define LN2   0.6931471805599453f

// ---- static scratch ----
// cost in diag layout [b][i+j][j], log2e-scaled, padded by 4 rows for branchless prefetch
__device__ float g_cost[64 * 512 * 256 + 1024];

__device__ __forceinline__ float ex2f(float x) {
    float y; asm("ex2.approx.f32 %0, %1;" : "=f"(y) : "f"(x)); return y;
}
__device__ __forceinline__ float lg2f(float x) {
    float y; asm("lg2.approx.f32 %0, %1;" : "=f"(y) : "f"(x)); return y;
}
__device__ __forceinline__ uint32_t sptr(const void* p) {
    return (uint32_t)__cvta_generic_to_shared(p);
}
// stable soft-min of 3 in log2 domain
__device__ __forceinline__ float sm3(float a, float b, float c) {
    float mn = fminf(a, b), mx = fmaxf(a, b);
    float lo  = fminf(mn, c);
    float mid = fmaxf(mn, fminf(mx, c));
    float hi  = fmaxf(mx, c);
    return lo - lg2f(1.0f + ex2f(lo - mid) + ex2f(lo - hi));
}

// ================= K1: fused norms + bf16 mma cost GEMM =================
// 256 blocks = 64 batches x (2x2 tiles of 128x128). 8 warps, warp tile 32(m) x 64(n).
// Loads fp32 X/Y directly; converts to bf16 for mma; accumulates per-row |.|^2 in
// registers, reduced via width-16 shfl into smem norms consumed by the epilogue.
__global__ void __launch_bounds__(256) cost_gemm_kernel(const float* __restrict__ X,
                                                        const float* __restrict__ Y,
                                                        float* __restrict__ out) {
    __shared__ __align__(16) char smraw[33280];
    unsigned short* Xs = (unsigned short*)smraw;       // [128][64] bf16, swizzled
    unsigned short* Ys = Xs + 128 * 64;
    float* Cs = (float*)smraw;                          // [64][130] (aliases Xs/Ys)
    __shared__ float xnorm[128], ynorm[128];            // log2e * |row|^2 (local tile idx)

    int bx = blockIdx.x;
    int b = bx >> 2, tm = (bx >> 1) & 1, tn = bx & 1;
    int t = threadIdx.x, lane = t & 31, w = t >> 5;
    int wr = w >> 1, wc = w & 1;

    if (bx == 0 && t == 0) out[0] = 0.f;

    const float* Xg = X + (size_t)(b * 256 + tm * 128) * 128;
    const float* Yg = Y + (size_t)(b * 256 + tn * 128) * 128;

    float acc[2][8][4];
#pragma unroll
    for (int am = 0; am < 2; am++)
#pragma unroll
        for (int bn = 0; bn < 8; bn++)
#pragma unroll
            for (int k = 0; k < 4; k++) acc[am][bn][k] = 0.f;

    float rsx[8], rsy[8];
#pragma unroll
    for (int p = 0; p < 8; p++) { rsx[p] = 0.f; rsy[p] = 0.f; }

    int arow0 = 32 * wr + (lane & 15);
    int ahalf = lane >> 4;
    int brow0 = 64 * wc + (lane & 7) + ((lane >> 4) << 3);
    int bhalf = (lane >> 3) & 1;

    int lrow = t >> 4;     // base row (0..15); rows covered: lrow + 16p
    int c4 = t & 15;       // float4 slot within 64-col chunk

    for (int kc = 0; kc < 128; kc += 64) {
        __syncthreads();
        // X tile: fp32 load -> norm partial -> bf16 swizzled store
#pragma unroll
        for (int p = 0; p < 8; p++) {
            int row = lrow + 16 * p;
            float4 f = *(const float4*)(Xg + (size_t)row * 128 + kc + c4 * 4);
            rsx[p] = fmaf(f.x, f.x, fmaf(f.y, f.y, fmaf(f.z, f.z, fmaf(f.w, f.w, rsx[p]))));
            ushort4 u;
            u.x = __bfloat16_as_ushort(__float2bfloat16(f.x));
            u.y = __bfloat16_as_ushort(__float2bfloat16(f.y));
            u.z = __bfloat16_as_ushort(__float2bfloat16(f.z));
            u.w = __bfloat16_as_ushort(__float2bfloat16(f.w));
            int soff = row * 128 + (((c4 >> 1) ^ (row & 7)) << 4) + (c4 & 1) * 8;
            *(ushort4*)((char*)Xs + soff) = u;
        }
        // Y tile
#pragma unroll
        for (int p = 0; p < 8; p++) {
            int row = lrow + 16 * p;
            float4 f = *(const float4*)(Yg + (size_t)row * 128 + kc + c4 * 4);
            rsy[p] = fmaf(f.x, f.x, fmaf(f.y, f.y, fmaf(f.z, f.z, fmaf(f.w, f.w, rsy[p]))));
            ushort4 u;
            u.x = __bfloat16_as_ushort(__float2bfloat16(f.x));
            u.y = __bfloat16_as_ushort(__float2bfloat16(f.y));
            u.z = __bfloat16_as_ushort(__float2bfloat16(f.z));
            u.w = __bfloat16_as_ushort(__float2bfloat16(f.w));
            int soff = row * 128 + (((c4 >> 1) ^ (row & 7)) << 4) + (c4 & 1) * 8;
            *(ushort4*)((char*)Ys + soff) = u;
        }
        __syncthreads();
#pragma unroll
        for (int ks = 0; ks < 4; ks++) {
            uint32_t a[2][4], bf[8][2];
#pragma unroll
            for (int am = 0; am < 2; am++) {
                int row = arow0 + 16 * am;
                int kb16 = ks * 2 + ahalf;
                uint32_t ad = sptr((char*)Xs + row * 128 + ((kb16 ^ (row & 7)) << 4));
                asm volatile("ldmatrix.sync.aligned.m8n8.x4.shared.b16 {%0,%1,%2,%3},[%4];"
                    : "=r"(a[am][0]), "=r"(a[am][1]), "=r"(a[am][2]), "=r"(a[am][3]) : "r"(ad));
            }
#pragma unroll
            for (int bp = 0; bp < 4; bp++) {
                int row = brow0 + 16 * bp;
                int kb16 = ks * 2 + bhalf;
                uint32_t ad = sptr((char*)Ys + row * 128 + ((kb16 ^ (row & 7)) << 4));
                asm volatile("ldmatrix.sync.aligned.m8n8.x4.shared.b16 {%0,%1,%2,%3},[%4];"
                    : "=r"(bf[2 * bp][0]), "=r"(bf[2 * bp][1]),
                      "=r"(bf[2 * bp + 1][0]), "=r"(bf[2 * bp + 1][1]) : "r"(ad));
            }
#pragma unroll
            for (int am = 0; am < 2; am++)
#pragma unroll
                for (int bn = 0; bn < 8; bn++)
                    asm volatile("mma.sync.aligned.m16n8k16.row.col.f32.bf16.bf16.f32 "
                        "{%0,%1,%2,%3},{%4,%5,%6,%7},{%8,%9},{%0,%1,%2,%3};"
                        : "+f"(acc[am][bn][0]), "+f"(acc[am][bn][1]),
                          "+f"(acc[am][bn][2]), "+f"(acc[am][bn][3])
                        : "r"(a[am][0]), "r"(a[am][1]), "r"(a[am][2]), "r"(a[am][3]),
                          "r"(bf[bn][0]), "r"(bf[bn][1]));
        }
    }

    // norm reduction: width-16 shfl, single writer per row (deterministic)
#pragma unroll
    for (int p = 0; p < 8; p++) {
        float sx = rsx[p], sy = rsy[p];
#pragma unroll
        for (int off = 8; off >= 1; off >>= 1) {
            sx += __shfl_xor_sync(0xffffffffu, sx, off, 16);
            sy += __shfl_xor_sync(0xffffffffu, sy, off, 16);
        }
        if ((t & 15) == 0) {
            xnorm[lrow + 16 * p] = sx * LOG2E;
            ynorm[lrow + 16 * p] = sy * LOG2E;
        }
    }

    // epilogue: stage to smem in 2 row-halves, then coalesced diag-major stores
    __syncthreads();
    float* cb = g_cost + (size_t)b * 512 * 256;

#pragma unroll
    for (int h = 0; h < 2; h++) {
        if ((wr >> 1) == h) {
            int rbase = 32 * (wr & 1);
#pragma unroll
            for (int am = 0; am < 2; am++)
#pragma unroll
                for (int bn = 0; bn < 8; bn++) {
                    int rr = rbase + 16 * am + (lane >> 2);
                    int cc = 64 * wc + 8 * bn + 2 * (lane & 3);
                    *(float2*)&Cs[rr * 130 + cc] = make_float2(acc[am][bn][0], acc[am][bn][1]);
                    *(float2*)&Cs[(rr + 8) * 130 + cc] = make_float2(acc[am][bn][2], acc[am][bn][3]);
                }
        }
        __syncthreads();
        int tt = t & 127;
        for (int s2 = 0; s2 < 192; s2 += 2) {
            int s = s2 + (t >> 7);                 // local diag within half: 0..191
            int lj_lo = max(0, s - 63), lj_hi = min(127, s);
            int lj = lj_lo + tt;
            if (s < 191 && lj <= lj_hi) {
                int li = s - lj;
                int i = tm * 128 + 64 * h + li;
                int j = tn * 128 + lj;
                float v = xnorm[64 * h + li] + ynorm[lj] - (2.0f * LOG2E) * Cs[li * 130 + lj];
                cb[(size_t)(i + j) * 256 + j] = v;
            }
        }
        __syncthreads();
    }
}

// ================= K2: 2-diagonal-per-barrier wavefront soft-DTW (R10 best) =================
// 64 blocks (1/batch) x 128 threads (4 warps). Thread t owns columns jA=2t+1, jB=2t+2.
__global__ void __launch_bounds__(128) dp_kernel(float* __restrict__ out) {
    __shared__ float4 bndP[2][5];   // [parity][slot] {r1A,r2A,r1B,r2B} of warp slot-1's lane31
    __shared__ float  bndC[2][5];   // cost element for the redundant boundary cell

    int t = threadIdx.x, lane = t & 31, w = t >> 5, b = blockIdx.x;
    const float INF = __int_as_float(0x7f800000);
    const float* cost = g_cost + (size_t)b * 512 * 256 + 2 * t;

    if (t < 10) {
        ((float4*)bndP)[t] = make_float4(INF, INF, INF, INF);
        ((float*)bndC)[t] = 0.0f;
    }
    __syncthreads();

    float r1A = INF, r2A = INF, r1B = INF, r2B = INF;
    float2 e0 = *(const float2*)(cost + 0 * 256);   // row 2k   (d-2)
    float2 o0 = *(const float2*)(cost + 1 * 256);   // row 2k+1 (d-1)
    float2 e1 = *(const float2*)(cost + 2 * 256);
    float2 o1 = *(const float2*)(cost + 3 * 256);

    int jA = 2 * t + 1;
    bool p0 = (t == 0);
    bool isL0 = (lane == 0);
    bool isL31 = (lane == 31);
    int jR = 64 * w;                 // boundary column left of this warp

    for (int k = 0; k < 256; ++k) {
        int d = 2 * k + 2;
        int par = k & 1;

        float sh1 = __shfl_up_sync(0xffffffffu, r1B, 1);
        float sh2 = __shfl_up_sync(0xffffffffu, r2B, 1);
        float4 P = bndP[par][w];     // uniform per warp (broadcast)
        float Pc = bndC[par][w];
        float lbA1 = isL0 ? P.z : sh1;     // R[d-1][jA-1]
        float lbA2 = isL0 ? P.w : sh2;     // R[d-2][jA-1]
        if (p0) { lbA1 = INF; lbA2 = (k == 0) ? 0.0f : INF; }

        // ---- diagonal d ----
        float rdA = e0.x + sm3(r1A, lbA1, lbA2);
        float rdB = e0.y + sm3(r1B, r1A, r2A);
        float rr  = Pc  + sm3(P.z,  P.x,  P.y);    // redundant boundary cell (col jR, diag d)

        unsigned iA = (unsigned)(d - jA);
        float r1A_mid = ((iA - 1u) < 256u) ? rdA : r1A;   // R[d][jA] effective
        float r1B_mid = ((iA - 2u) < 256u) ? rdB : r1B;   // R[d][jB] effective
        float rr_eff  = ((unsigned)(d - jR - 1) < 256u) ? rr : INF;  // R[d][jR] eff

        // ---- diagonal d+1 ----
        float shm = __shfl_up_sync(0xffffffffu, r1B_mid, 1);
        float lbA1p = isL0 ? rr_eff : shm;  // R[d][jA-1]
        if (p0) lbA1p = INF;
        float rdAp = o0.x + sm3(r1A_mid, lbA1p, lbA1);     // dl = R[d-1][jA-1]
        float rdBp = o0.y + sm3(r1B_mid, r1A_mid, r1A);    // dl = R[d-1][jA]

        r2A = r1A_mid;
        r1A = ((iA + 0u) < 256u) ? rdAp : r1A_mid;   // (d+1)-jA - 1 = iA
        r2B = r1B_mid;
        r1B = ((iA - 1u) < 256u) ? rdBp : r1B_mid;   // (d+1)-jB - 1 = iA-1

        // publish for next iteration's consumer (warp w+1)
        if (isL31) {
            bndP[par ^ 1][w + 1] = make_float4(r1A, r2A, r1B, r2B);
            bndC[par ^ 1][w + 1] = e1.y;   // cost row 2k+2, col jB-1
        }
        __syncthreads();

        // shift cost pipeline (pad rows make this branchless-safe)
        e0 = e1; o0 = o1;
        e1 = *(const float2*)(cost + (size_t)(2 * k + 4) * 256);
        o1 = *(const float2*)(cost + (size_t)(2 * k + 5) * 256);
    }

    // t=127 col jB=256: r1B = R[512][256]
    if (t == 127) atomicAdd(out, r1B * (LN2 / 64.0f));
}

extern "C" void kernel_launch(void* const* d_in, const int* in_sizes, int n_in,
                              void* d_out, int out_size) {
    const float* x = (const float*)d_in[0];
    const float* y = (const float*)d_in[1];
    float* out = (float*)d_out;
    cost_gemm_kernel<<<256, 256>>>(x, y, out);
    dp_kernel<<<64, 128>>>(out);
}

// round 15
// speedup vs baseline: 1.7142x; 1.3635x over previous
#include <cuda_runtime.h>
#include <cuda_bf16.h>
#include <cstdint>
#include <cstddef>

#define LOG2E 1.4426950408889634f
#define LN2   0.6931471805599453f

// ---- static scratch ----
// cost in diag layout [b][i+j][j], log2e-scaled, padded for deep branchless prefetch
__device__ float g_cost[64 * 512 * 256 + 4096];

__device__ __forceinline__ float ex2f(float x) {
    float y; asm("ex2.approx.f32 %0, %1;" : "=f"(y) : "f"(x)); return y;
}
__device__ __forceinline__ float lg2f(float x) {
    float y; asm("lg2.approx.f32 %0, %1;" : "=f"(y) : "f"(x)); return y;
}
__device__ __forceinline__ uint32_t sptr(const void* p) {
    return (uint32_t)__cvta_generic_to_shared(p);
}
// stable soft-min of 3 in log2 domain
__device__ __forceinline__ float sm3(float a, float b, float c) {
    float mn = fminf(a, b), mx = fmaxf(a, b);
    float lo  = fminf(mn, c);
    float mid = fmaxf(mn, fminf(mx, c));
    float hi  = fmaxf(mx, c);
    return lo - lg2f(1.0f + ex2f(lo - mid) + ex2f(lo - hi));
}

// ================= K1: fused norms + bf16 mma cost GEMM =================
// 256 blocks = 64 batches x (2x2 tiles of 128x128). 8 warps, warp tile 32(m) x 64(n).
__global__ void __launch_bounds__(256) cost_gemm_kernel(const float* __restrict__ X,
                                                        const float* __restrict__ Y,
                                                        float* __restrict__ out) {
    __shared__ __align__(16) char smraw[33280];
    unsigned short* Xs = (unsigned short*)smraw;       // [128][64] bf16, swizzled
    unsigned short* Ys = Xs + 128 * 64;
    float* Cs = (float*)smraw;                          // [64][130] (aliases Xs/Ys)
    __shared__ float xnorm[128], ynorm[128];            // log2e * |row|^2 (local tile idx)

    int bx = blockIdx.x;
    int b = bx >> 2, tm = (bx >> 1) & 1, tn = bx & 1;
    int t = threadIdx.x, lane = t & 31, w = t >> 5;
    int wr = w >> 1, wc = w & 1;

    if (bx == 0 && t == 0) out[0] = 0.f;

    const float* Xg = X + (size_t)(b * 256 + tm * 128) * 128;
    const float* Yg = Y + (size_t)(b * 256 + tn * 128) * 128;

    float acc[2][8][4];
#pragma unroll
    for (int am = 0; am < 2; am++)
#pragma unroll
        for (int bn = 0; bn < 8; bn++)
#pragma unroll
            for (int k = 0; k < 4; k++) acc[am][bn][k] = 0.f;

    float rsx[8], rsy[8];
#pragma unroll
    for (int p = 0; p < 8; p++) { rsx[p] = 0.f; rsy[p] = 0.f; }

    int arow0 = 32 * wr + (lane & 15);
    int ahalf = lane >> 4;
    int brow0 = 64 * wc + (lane & 7) + ((lane >> 4) << 3);
    int bhalf = (lane >> 3) & 1;

    int lrow = t >> 4;     // base row (0..15); rows covered: lrow + 16p
    int c4 = t & 15;       // float4 slot within 64-col chunk

    for (int kc = 0; kc < 128; kc += 64) {
        __syncthreads();
#pragma unroll
        for (int p = 0; p < 8; p++) {
            int row = lrow + 16 * p;
            float4 f = *(const float4*)(Xg + (size_t)row * 128 + kc + c4 * 4);
            rsx[p] = fmaf(f.x, f.x, fmaf(f.y, f.y, fmaf(f.z, f.z, fmaf(f.w, f.w, rsx[p]))));
            ushort4 u;
            u.x = __bfloat16_as_ushort(__float2bfloat16(f.x));
            u.y = __bfloat16_as_ushort(__float2bfloat16(f.y));
            u.z = __bfloat16_as_ushort(__float2bfloat16(f.z));
            u.w = __bfloat16_as_ushort(__float2bfloat16(f.w));
            int soff = row * 128 + (((c4 >> 1) ^ (row & 7)) << 4) + (c4 & 1) * 8;
            *(ushort4*)((char*)Xs + soff) = u;
        }
#pragma unroll
        for (int p = 0; p < 8; p++) {
            int row = lrow + 16 * p;
            float4 f = *(const float4*)(Yg + (size_t)row * 128 + kc + c4 * 4);
            rsy[p] = fmaf(f.x, f.x, fmaf(f.y, f.y, fmaf(f.z, f.z, fmaf(f.w, f.w, rsy[p]))));
            ushort4 u;
            u.x = __bfloat16_as_ushort(__float2bfloat16(f.x));
            u.y = __bfloat16_as_ushort(__float2bfloat16(f.y));
            u.z = __bfloat16_as_ushort(__float2bfloat16(f.z));
            u.w = __bfloat16_as_ushort(__float2bfloat16(f.w));
            int soff = row * 128 + (((c4 >> 1) ^ (row & 7)) << 4) + (c4 & 1) * 8;
            *(ushort4*)((char*)Ys + soff) = u;
        }
        __syncthreads();
#pragma unroll
        for (int ks = 0; ks < 4; ks++) {
            uint32_t a[2][4], bf[8][2];
#pragma unroll
            for (int am = 0; am < 2; am++) {
                int row = arow0 + 16 * am;
                int kb16 = ks * 2 + ahalf;
                uint32_t ad = sptr((char*)Xs + row * 128 + ((kb16 ^ (row & 7)) << 4));
                asm volatile("ldmatrix.sync.aligned.m8n8.x4.shared.b16 {%0,%1,%2,%3},[%4];"
                    : "=r"(a[am][0]), "=r"(a[am][1]), "=r"(a[am][2]), "=r"(a[am][3]) : "r"(ad));
            }
#pragma unroll
            for (int bp = 0; bp < 4; bp++) {
                int row = brow0 + 16 * bp;
                int kb16 = ks * 2 + bhalf;
                uint32_t ad = sptr((char*)Ys + row * 128 + ((kb16 ^ (row & 7)) << 4));
                asm volatile("ldmatrix.sync.aligned.m8n8.x4.shared.b16 {%0,%1,%2,%3},[%4];"
                    : "=r"(bf[2 * bp][0]), "=r"(bf[2 * bp][1]),
                      "=r"(bf[2 * bp + 1][0]), "=r"(bf[2 * bp + 1][1]) : "r"(ad));
            }
#pragma unroll
            for (int am = 0; am < 2; am++)
#pragma unroll
                for (int bn = 0; bn < 8; bn++)
                    asm volatile("mma.sync.aligned.m16n8k16.row.col.f32.bf16.bf16.f32 "
                        "{%0,%1,%2,%3},{%4,%5,%6,%7},{%8,%9},{%0,%1,%2,%3};"
                        : "+f"(acc[am][bn][0]), "+f"(acc[am][bn][1]),
                          "+f"(acc[am][bn][2]), "+f"(acc[am][bn][3])
                        : "r"(a[am][0]), "r"(a[am][1]), "r"(a[am][2]), "r"(a[am][3]),
                          "r"(bf[bn][0]), "r"(bf[bn][1]));
        }
    }

    // norm reduction: width-16 shfl, single writer per row (deterministic)
#pragma unroll
    for (int p = 0; p < 8; p++) {
        float sx = rsx[p], sy = rsy[p];
#pragma unroll
        for (int off = 8; off >= 1; off >>= 1) {
            sx += __shfl_xor_sync(0xffffffffu, sx, off, 16);
            sy += __shfl_xor_sync(0xffffffffu, sy, off, 16);
        }
        if ((t & 15) == 0) {
            xnorm[lrow + 16 * p] = sx * LOG2E;
            ynorm[lrow + 16 * p] = sy * LOG2E;
        }
    }

    // epilogue: stage to smem in 2 row-halves, then coalesced diag-major stores
    __syncthreads();
    float* cb = g_cost + (size_t)b * 512 * 256;

#pragma unroll
    for (int h = 0; h < 2; h++) {
        if ((wr >> 1) == h) {
            int rbase = 32 * (wr & 1);
#pragma unroll
            for (int am = 0; am < 2; am++)
#pragma unroll
                for (int bn = 0; bn < 8; bn++) {
                    int rr = rbase + 16 * am + (lane >> 2);
                    int cc = 64 * wc + 8 * bn + 2 * (lane & 3);
                    *(float2*)&Cs[rr * 130 + cc] = make_float2(acc[am][bn][0], acc[am][bn][1]);
                    *(float2*)&Cs[(rr + 8) * 130 + cc] = make_float2(acc[am][bn][2], acc[am][bn][3]);
                }
        }
        __syncthreads();
        int tt = t & 127;
        for (int s2 = 0; s2 < 192; s2 += 2) {
            int s = s2 + (t >> 7);                 // local diag within half: 0..191
            int lj_lo = max(0, s - 63), lj_hi = min(127, s);
            int lj = lj_lo + tt;
            if (s < 191 && lj <= lj_hi) {
                int li = s - lj;
                int i = tm * 128 + 64 * h + li;
                int j = tn * 128 + lj;
                float v = xnorm[64 * h + li] + ynorm[lj] - (2.0f * LOG2E) * Cs[li * 130 + lj];
                cb[(size_t)(i + j) * 256 + j] = v;
            }
        }
        __syncthreads();
    }
}

// ================= K2: 2-diag-per-barrier wavefront soft-DTW, depth-3 prefetch ========
// 64 blocks (1/batch) x 128 threads (4 warps). Thread t owns columns jA=2t+1, jB=2t+2.
// Cost rows held in a 4-slot register ring loaded 3 iterations ahead (covers DRAM lat).
__global__ void __launch_bounds__(128) dp_kernel(float* __restrict__ out) {
    __shared__ float4 bndP[2][5];   // [parity][slot] {r1A,r2A,r1B,r2B} of warp slot-1's lane31
    __shared__ float  bndC[2][5];   // cost element for the redundant boundary cell

    int t = threadIdx.x, lane = t & 31, w = t >> 5, b = blockIdx.x;
    const float INF = __int_as_float(0x7f800000);
    const float* cost = g_cost + (size_t)b * 512 * 256 + 2 * t;

    if (t < 10) {
        ((float4*)bndP)[t] = make_float4(INF, INF, INF, INF);
        ((float*)bndC)[t] = 0.0f;
    }
    __syncthreads();

    float r1A = INF, r2A = INF, r1B = INF, r2B = INF;

    float2 eb[4], ob[4];              // ring: slot k&3 feeds iteration k
#pragma unroll
    for (int i = 0; i < 3; i++) {
        eb[i] = *(const float2*)(cost + (size_t)(2 * i) * 256);
        ob[i] = *(const float2*)(cost + (size_t)(2 * i + 1) * 256);
    }

    int jA = 2 * t + 1;
    bool p0 = (t == 0);
    bool isL0 = (lane == 0);
    bool isL31 = (lane == 31);
    int jR = 64 * w;                 // boundary column left of this warp

#pragma unroll 4
    for (int k = 0; k < 256; ++k) {
        int d = 2 * k + 2;
        int par = k & 1;

        // issue depth-3 prefetch FIRST (rows 2k+6, 2k+7; pad keeps this in-bounds)
        eb[(k + 3) & 3] = *(const float2*)(cost + (size_t)(2 * k + 6) * 256);
        ob[(k + 3) & 3] = *(const float2*)(cost + (size_t)(2 * k + 7) * 256);

        float2 e0 = eb[k & 3];
        float2 o0 = ob[k & 3];

        float sh1 = __shfl_up_sync(0xffffffffu, r1B, 1);
        float sh2 = __shfl_up_sync(0xffffffffu, r2B, 1);
        float4 P = bndP[par][w];     // uniform per warp (broadcast)
        float Pc = bndC[par][w];
        float lbA1 = isL0 ? P.z : sh1;     // R[d-1][jA-1]
        float lbA2 = isL0 ? P.w : sh2;     // R[d-2][jA-1]
        if (p0) { lbA1 = INF; lbA2 = (k == 0) ? 0.0f : INF; }

        // ---- diagonal d ----
        float rdA = e0.x + sm3(r1A, lbA1, lbA2);
        float rdB = e0.y + sm3(r1B, r1A, r2A);
        float rr  = Pc  + sm3(P.z,  P.x,  P.y);    // redundant boundary cell (col jR, diag d)

        unsigned iA = (unsigned)(d - jA);
        float r1A_mid = ((iA - 1u) < 256u) ? rdA : r1A;   // R[d][jA] effective
        float r1B_mid = ((iA - 2u) < 256u) ? rdB : r1B;   // R[d][jB] effective
        float rr_eff  = ((unsigned)(d - jR - 1) < 256u) ? rr : INF;  // R[d][jR] eff

        // ---- diagonal d+1 ----
        float shm = __shfl_up_sync(0xffffffffu, r1B_mid, 1);
        float lbA1p = isL0 ? rr_eff : shm;  // R[d][jA-1]
        if (p0) lbA1p = INF;
        float rdAp = o0.x + sm3(r1A_mid, lbA1p, lbA1);     // dl = R[d-1][jA-1]
        float rdBp = o0.y + sm3(r1B_mid, r1A_mid, r1A);    // dl = R[d-1][jA]

        r2A = r1A_mid;
        r1A = ((iA + 0u) < 256u) ? rdAp : r1A_mid;   // (d+1)-jA - 1 = iA
        r2B = r1B_mid;
        r1B = ((iA - 1u) < 256u) ? rdBp : r1B_mid;   // (d+1)-jB - 1 = iA-1

        // publish for next iteration's consumer (warp w+1); cost row 2k+2 = eb[(k+1)&3]
        if (isL31) {
            bndP[par ^ 1][w + 1] = make_float4(r1A, r2A, r1B, r2B);
            bndC[par ^ 1][w + 1] = eb[(k + 1) & 3].y;
        }
        __syncthreads();
    }

    // t=127 col jB=256: r1B = R[512][256]
    if (t == 127) atomicAdd(out, r1B * (LN2 / 64.0f));
}

extern "C" void kernel_launch(void* const* d_in, const int* in_sizes, int n_in,
                              void* d_out, int out_size) {
    const float* x = (const float*)d_in[0];
    const float* y = (const float*)d_in[1];
    float* out = (float*)d_out;
    cost_gemm_kernel<<<256, 256>>>(x, y, out);
    dp_kernel<<<64, 128>>>(out);
}